// round 2
// baseline (speedup 1.0000x reference)
#include <cuda_runtime.h>

#define D 128
#define NMAX 100000
#define EMAX 1600000

// Scratch (device globals — no runtime allocation allowed)
__device__ float g_xl[(size_t)NMAX * D];   // x @ W_l
__device__ float g_xr[(size_t)NMAX * D];   // x @ W_r
__device__ float g_agg[(size_t)NMAX * D];  // segment sum of xl[src]*invdeg[dst]
__device__ float g_h[(size_t)NMAX * D];    // layer-1 output
__device__ float g_deg[NMAX];              // degree, then 1/max(deg,1)

// ---------------------------------------------------------------------------
__global__ void init_kernel(int N) {
    int i = blockIdx.x * blockDim.x + threadIdx.x;
    int total = N * D;
    if (i < total) g_agg[i] = 0.f;
    if (i < N) g_deg[i] = 0.f;
}

__global__ void deg_kernel(const int* __restrict__ ei, int E) {
    int e = blockIdx.x * blockDim.x + threadIdx.x;
    if (e < E) atomicAdd(&g_deg[ei[E + e]], 1.0f);
}

__global__ void invdeg_kernel(int N) {
    int i = blockIdx.x * blockDim.x + threadIdx.x;
    if (i < N) g_deg[i] = 1.0f / fmaxf(g_deg[i], 1.0f);
}

// ---------------------------------------------------------------------------
// Dual GEMM: xl = A @ B1, xr = A @ B2.  A is [M,128], B's are [128,128].
// Tile: BM=64 rows x full N=128 cols per block, 256 threads,
// each thread computes an 8x4 microtile for BOTH outputs.
#define BM 64
#define BK 16

__global__ __launch_bounds__(256) void gemm_dual_kernel(
    const float* __restrict__ x_ext,
    const float* __restrict__ B1, const float* __restrict__ B2,
    int layer, int M)
{
    const float* __restrict__ A = (layer == 0) ? x_ext : g_h;

    __shared__ float As[BM * BK];       // [m][k]
    __shared__ float Bs1[BK * D];       // [k][n]
    __shared__ float Bs2[BK * D];

    int tid = threadIdx.x;
    int tx = tid & 31;    // col group: cols tx*4 .. tx*4+3
    int ty = tid >> 5;    // row group: rows ty*8 .. ty*8+7
    int row0 = blockIdx.x * BM;

    float acc1[8][4];
    float acc2[8][4];
#pragma unroll
    for (int i = 0; i < 8; i++)
#pragma unroll
        for (int j = 0; j < 4; j++) { acc1[i][j] = 0.f; acc2[i][j] = 0.f; }

    for (int kt = 0; kt < D; kt += BK) {
        // Load A tile 64x16 (one float4 per thread), row-major [m][k]
        {
            int r = tid >> 2;            // 0..63
            int kq = (tid & 3) * 4;      // 0,4,8,12
            float4 v = make_float4(0.f, 0.f, 0.f, 0.f);
            int gr = row0 + r;
            if (gr < M) v = *(const float4*)(A + (size_t)gr * D + kt + kq);
            *(float4*)(As + r * BK + kq) = v;
        }
        // Load B tiles 16x128 each (2 float4 per thread per B)
#pragma unroll
        for (int i = 0; i < 2; i++) {
            int idx = tid + i * 256;     // f4 index 0..511
            int k = idx >> 5;
            int n4 = (idx & 31) * 4;
            *(float4*)(Bs1 + k * D + n4) = *(const float4*)(B1 + (size_t)(kt + k) * D + n4);
            *(float4*)(Bs2 + k * D + n4) = *(const float4*)(B2 + (size_t)(kt + k) * D + n4);
        }
        __syncthreads();

#pragma unroll
        for (int k = 0; k < BK; k++) {
            float a[8];
#pragma unroll
            for (int i = 0; i < 8; i++) a[i] = As[(ty * 8 + i) * BK + k];
            float4 b1 = *(float4*)(Bs1 + k * D + tx * 4);
            float4 b2 = *(float4*)(Bs2 + k * D + tx * 4);
#pragma unroll
            for (int i = 0; i < 8; i++) {
                acc1[i][0] += a[i] * b1.x; acc1[i][1] += a[i] * b1.y;
                acc1[i][2] += a[i] * b1.z; acc1[i][3] += a[i] * b1.w;
                acc2[i][0] += a[i] * b2.x; acc2[i][1] += a[i] * b2.y;
                acc2[i][2] += a[i] * b2.z; acc2[i][3] += a[i] * b2.w;
            }
        }
        __syncthreads();
    }

#pragma unroll
    for (int i = 0; i < 8; i++) {
        int gr = row0 + ty * 8 + i;
        if (gr < M) {
            *(float4*)(g_xl + (size_t)gr * D + tx * 4) =
                make_float4(acc1[i][0], acc1[i][1], acc1[i][2], acc1[i][3]);
            *(float4*)(g_xr + (size_t)gr * D + tx * 4) =
                make_float4(acc2[i][0], acc2[i][1], acc2[i][2], acc2[i][3]);
        }
    }
}

// ---------------------------------------------------------------------------
// One warp per edge: 32 lanes cover 128 floats as float4 each.
// agg[dst] += xl[src] * invdeg[dst] via red.global.add.v4.f32
__global__ void scatter_kernel(const int* __restrict__ ei, int E) {
    long long t = (long long)blockIdx.x * blockDim.x + threadIdx.x;
    int e = (int)(t >> 5);
    if (e >= E) return;
    int c = ((int)t & 31) * 4;
    int s = ei[e];
    int d = ei[E + e];
    float w = __ldg(&g_deg[d]);
    float4 v = *(const float4*)(g_xl + (size_t)s * D + c);
    float* p = g_agg + (size_t)d * D + c;
    asm volatile("red.global.add.v4.f32 [%0], {%1, %2, %3, %4};"
                 :: "l"(p), "f"(v.x * w), "f"(v.y * w), "f"(v.z * w), "f"(v.w * w)
                 : "memory");
}

// ---------------------------------------------------------------------------
// out = relu(agg + xr + b). Layer 0 writes g_h and re-zeros g_agg for layer 1.
__global__ void finish_kernel(const float* __restrict__ b, float* __restrict__ out_ext,
                              int layer, int total) {
    int i = blockIdx.x * blockDim.x + threadIdx.x;
    if (i >= total) return;
    float v = g_agg[i] + g_xr[i] + __ldg(&b[i & (D - 1)]);
    v = fmaxf(v, 0.f);
    if (layer == 0) {
        g_h[i] = v;
        g_agg[i] = 0.f;   // ready for layer 2
    } else {
        out_ext[i] = v;
    }
}

// ---------------------------------------------------------------------------
extern "C" void kernel_launch(void* const* d_in, const int* in_sizes, int n_in,
                              void* d_out, int out_size) {
    const float* x       = (const float*)d_in[0];
    const int*   ei      = (const int*)d_in[1];    // int32! (JAX demotes int64 without x64)
    const float* W_l1    = (const float*)d_in[2];
    const float* W_r1    = (const float*)d_in[3];
    const float* b1      = (const float*)d_in[4];
    const float* W_l2    = (const float*)d_in[5];
    const float* W_r2    = (const float*)d_in[6];
    const float* b2      = (const float*)d_in[7];
    float* out           = (float*)d_out;

    int N = in_sizes[0] / D;       // 100000
    int E = in_sizes[1] / 2;       // 1600000
    int total = N * D;

    int tb = 256;
    int grid_total   = (total + tb - 1) / tb;
    int grid_E       = (E + tb - 1) / tb;
    int grid_gemm    = (N + BM - 1) / BM;
    long long sthreads = (long long)E * 32;
    int grid_scatter = (int)((sthreads + tb - 1) / tb);

    // Degree (once) + zero accumulators
    init_kernel<<<grid_total, tb>>>(N);
    deg_kernel<<<grid_E, tb>>>(ei, E);
    invdeg_kernel<<<(N + tb - 1) / tb, tb>>>(N);

    // Layer 1
    gemm_dual_kernel<<<grid_gemm, 256>>>(x, W_l1, W_r1, 0, N);
    scatter_kernel<<<grid_scatter, tb>>>(ei, E);
    finish_kernel<<<grid_total, tb>>>(b1, out, 0, total);

    // Layer 2
    gemm_dual_kernel<<<grid_gemm, 256>>>(x, W_l2, W_r2, 1, N);
    scatter_kernel<<<grid_scatter, tb>>>(ei, E);
    finish_kernel<<<grid_total, tb>>>(b2, out, 1, total);
}

// round 3
// speedup vs baseline: 1.9491x; 1.9491x over previous
#include <cuda_runtime.h>

#define D 128
#define NMAX 100000
#define EMAX 1600000
#define SCH 512          // scan chunk per block

// Scratch (device globals — no runtime allocation allowed)
__device__ float g_xl[(size_t)NMAX * D];   // A @ W_l
__device__ float g_xr[(size_t)NMAX * D];   // A @ W_r
__device__ float g_h [(size_t)NMAX * D];   // layer-1 output
__device__ float g_inv[NMAX];              // 1/max(deg,1)
__device__ int   g_cnt[NMAX];              // degree counts
__device__ int   g_fill[NMAX];             // bucket fill cursors
__device__ int   g_rowptr[NMAX + 1];       // CSR row pointers (by dst)
__device__ int   g_srcs[EMAX];             // src node per CSR slot
__device__ int   g_bsum[256];              // per-block scan partials

// ---------------------------------------------------------------------------
// CSR build: histogram -> 2-level scan -> fill
// ---------------------------------------------------------------------------
__global__ void zero_cnt_kernel(int N) {
    int i = blockIdx.x * blockDim.x + threadIdx.x;
    if (i < N) g_cnt[i] = 0;
}

__global__ void hist_kernel(const int* __restrict__ ei, int E) {
    int e = blockIdx.x * blockDim.x + threadIdx.x;
    if (e < E) atomicAdd(&g_cnt[ei[E + e]], 1);
}

// Block-local inclusive scan of SCH counts; writes rowptr[i+1] (pre-fixup) + block sum
__global__ __launch_bounds__(SCH) void scan1_kernel(int N) {
    __shared__ int sh[SCH];
    int t = threadIdx.x;
    int base = blockIdx.x * SCH;
    int gi = base + t;
    sh[t] = (gi < N) ? g_cnt[gi] : 0;
    __syncthreads();
#pragma unroll
    for (int off = 1; off < SCH; off <<= 1) {
        int y = (t >= off) ? sh[t - off] : 0;
        __syncthreads();
        sh[t] += y;
        __syncthreads();
    }
    if (gi < N) g_rowptr[gi + 1] = sh[t];
    if (t == SCH - 1) g_bsum[blockIdx.x] = sh[t];
}

// Scan of block sums -> exclusive offsets (nblocks <= 256)
__global__ __launch_bounds__(256) void scan2_kernel(int nblocks) {
    __shared__ int sh[256];
    int t = threadIdx.x;
    sh[t] = (t < nblocks) ? g_bsum[t] : 0;
    __syncthreads();
#pragma unroll
    for (int off = 1; off < 256; off <<= 1) {
        int y = (t >= off) ? sh[t - off] : 0;
        __syncthreads();
        sh[t] += y;
        __syncthreads();
    }
    if (t < nblocks) g_bsum[t] = (t > 0) ? sh[t - 1] : 0;  // exclusive
}

// Fixup rowptr with block offsets; also compute invdeg, zero fill cursors
__global__ void scan3_kernel(int N) {
    int i = blockIdx.x * blockDim.x + threadIdx.x;
    if (i >= N) return;
    g_rowptr[i + 1] += g_bsum[i / SCH];
    g_inv[i] = 1.0f / fmaxf((float)g_cnt[i], 1.0f);
    g_fill[i] = 0;
    if (i == 0) g_rowptr[0] = 0;
}

__global__ void fill_kernel(const int* __restrict__ ei, int E) {
    int e = blockIdx.x * blockDim.x + threadIdx.x;
    if (e >= E) return;
    int d = ei[E + e];
    int pos = g_rowptr[d] + atomicAdd(&g_fill[d], 1);
    g_srcs[pos] = ei[e];
}

// ---------------------------------------------------------------------------
// Dual GEMM via packed fma.rn.f32x2: xl = A@B1, xr = A@B2.
// BM=64 rows x 128 cols per 256-thread block; thread microtile = 8x4 per output,
// held as 4 row-pair x 4 col packed f32x2 accumulators.
// ---------------------------------------------------------------------------
#define BM 64
#define BK 16

#define FFMA2(acc, a, b) \
    asm("fma.rn.f32x2 %0, %1, %2, %0;" : "+l"(acc) : "l"(a), "l"(b))
#define DUP2(dst, s) \
    asm("mov.b64 %0, {%1, %1};" : "=l"(dst) : "f"(s))
#define UNPK2(lo, hi, v) \
    asm("mov.b64 {%0, %1}, %2;" : "=f"(lo), "=f"(hi) : "l"(v))

__global__ __launch_bounds__(256) void gemm_dual_kernel(
    const float* __restrict__ x_ext,
    const float* __restrict__ B1, const float* __restrict__ B2,
    int layer, int M)
{
    const float* __restrict__ A = (layer == 0) ? x_ext : g_h;

    __shared__ float As[BK][BM];     // k-major: pairs of consecutive m pack for free
    __shared__ float Bs1[BK][D];
    __shared__ float Bs2[BK][D];

    int tid = threadIdx.x;
    int tx = tid & 31;    // cols tx*4 .. tx*4+3
    int ty = tid >> 5;    // rows ty*8 .. ty*8+7
    int row0 = blockIdx.x * BM;

    unsigned long long acc1[4][4], acc2[4][4];
#pragma unroll
    for (int p = 0; p < 4; p++)
#pragma unroll
        for (int j = 0; j < 4; j++) { acc1[p][j] = 0ULL; acc2[p][j] = 0ULL; }

    for (int kt = 0; kt < D; kt += BK) {
        // A tile 64x16 -> transposed store As[k][m]
        {
            int r = tid >> 2;            // 0..63
            int kq = (tid & 3) * 4;      // 0,4,8,12
            float4 v = make_float4(0.f, 0.f, 0.f, 0.f);
            int gr = row0 + r;
            if (gr < M) v = *(const float4*)(A + (size_t)gr * D + kt + kq);
            As[kq + 0][r] = v.x;
            As[kq + 1][r] = v.y;
            As[kq + 2][r] = v.z;
            As[kq + 3][r] = v.w;
        }
        // B tiles 16x128 each
#pragma unroll
        for (int i = 0; i < 2; i++) {
            int idx = tid + i * 256;
            int k = idx >> 5;
            int n4 = (idx & 31) * 4;
            *(float4*)(&Bs1[k][n4]) = *(const float4*)(B1 + (size_t)(kt + k) * D + n4);
            *(float4*)(&Bs2[k][n4]) = *(const float4*)(B2 + (size_t)(kt + k) * D + n4);
        }
        __syncthreads();

#pragma unroll
        for (int k = 0; k < BK; k++) {
            // row pairs (broadcast LDS.128: all lanes in warp share ty)
            ulonglong2 a01 = *(const ulonglong2*)&As[k][ty * 8];
            ulonglong2 a23 = *(const ulonglong2*)&As[k][ty * 8 + 4];
            unsigned long long ap[4] = {a01.x, a01.y, a23.x, a23.y};

            float4 b1v = *(const float4*)&Bs1[k][tx * 4];
            float4 b2v = *(const float4*)&Bs2[k][tx * 4];
            unsigned long long bb1[4], bb2[4];
            DUP2(bb1[0], b1v.x); DUP2(bb1[1], b1v.y); DUP2(bb1[2], b1v.z); DUP2(bb1[3], b1v.w);
            DUP2(bb2[0], b2v.x); DUP2(bb2[1], b2v.y); DUP2(bb2[2], b2v.z); DUP2(bb2[3], b2v.w);

#pragma unroll
            for (int p = 0; p < 4; p++) {
#pragma unroll
                for (int j = 0; j < 4; j++) {
                    FFMA2(acc1[p][j], ap[p], bb1[j]);
                    FFMA2(acc2[p][j], ap[p], bb2[j]);
                }
            }
        }
        __syncthreads();
    }

    // Epilogue: unpack row pairs and store float4 per row
#pragma unroll
    for (int p = 0; p < 4; p++) {
        int gr0 = row0 + ty * 8 + 2 * p;
        float l0[4], h0[4], l1[4], h1[4];
#pragma unroll
        for (int j = 0; j < 4; j++) {
            UNPK2(l0[j], h0[j], acc1[p][j]);
            UNPK2(l1[j], h1[j], acc2[p][j]);
        }
        if (gr0 < M) {
            *(float4*)(g_xl + (size_t)gr0 * D + tx * 4) = make_float4(l0[0], l0[1], l0[2], l0[3]);
            *(float4*)(g_xr + (size_t)gr0 * D + tx * 4) = make_float4(l1[0], l1[1], l1[2], l1[3]);
        }
        if (gr0 + 1 < M) {
            *(float4*)(g_xl + (size_t)(gr0 + 1) * D + tx * 4) = make_float4(h0[0], h0[1], h0[2], h0[3]);
            *(float4*)(g_xr + (size_t)(gr0 + 1) * D + tx * 4) = make_float4(h1[0], h1[1], h1[2], h1[3]);
        }
    }
}

// ---------------------------------------------------------------------------
// Fused aggregate + epilogue: one warp per dst node.
// out[n] = relu( (sum_{s in N(n)} xl[s]) * inv[n] + xr[n] + b )
// ---------------------------------------------------------------------------
__global__ __launch_bounds__(256) void agg_finish_kernel(
    const float* __restrict__ b, float* __restrict__ out_ext,
    int layer, int N)
{
    long long t = (long long)blockIdx.x * blockDim.x + threadIdx.x;
    int n = (int)(t >> 5);
    if (n >= N) return;
    int c = ((int)t & 31) * 4;

    float4 acc = make_float4(0.f, 0.f, 0.f, 0.f);
    int s = g_rowptr[n];
    int e = g_rowptr[n + 1];
    int i = s;
    for (; i + 1 < e; i += 2) {
        int s0 = g_srcs[i];
        int s1 = g_srcs[i + 1];
        float4 v0 = *(const float4*)(g_xl + (size_t)s0 * D + c);
        float4 v1 = *(const float4*)(g_xl + (size_t)s1 * D + c);
        acc.x += v0.x + v1.x; acc.y += v0.y + v1.y;
        acc.z += v0.z + v1.z; acc.w += v0.w + v1.w;
    }
    if (i < e) {
        int s0 = g_srcs[i];
        float4 v0 = *(const float4*)(g_xl + (size_t)s0 * D + c);
        acc.x += v0.x; acc.y += v0.y; acc.z += v0.z; acc.w += v0.w;
    }

    float inv = g_inv[n];
    float4 xr = *(const float4*)(g_xr + (size_t)n * D + c);
    float4 bv = *(const float4*)(b + c);
    float4 r;
    r.x = fmaxf(fmaf(acc.x, inv, xr.x + bv.x), 0.f);
    r.y = fmaxf(fmaf(acc.y, inv, xr.y + bv.y), 0.f);
    r.z = fmaxf(fmaf(acc.z, inv, xr.z + bv.z), 0.f);
    r.w = fmaxf(fmaf(acc.w, inv, xr.w + bv.w), 0.f);

    float* dst = (layer == 0) ? g_h : out_ext;
    *(float4*)(dst + (size_t)n * D + c) = r;
}

// ---------------------------------------------------------------------------
extern "C" void kernel_launch(void* const* d_in, const int* in_sizes, int n_in,
                              void* d_out, int out_size) {
    const float* x    = (const float*)d_in[0];
    const int*   ei   = (const int*)d_in[1];    // int32 (JAX demotes int64)
    const float* W_l1 = (const float*)d_in[2];
    const float* W_r1 = (const float*)d_in[3];
    const float* b1   = (const float*)d_in[4];
    const float* W_l2 = (const float*)d_in[5];
    const float* W_r2 = (const float*)d_in[6];
    const float* b2   = (const float*)d_in[7];
    float* out        = (float*)d_out;

    int N = in_sizes[0] / D;   // 100000
    int E = in_sizes[1] / 2;   // 1600000

    int tb = 256;
    int grid_N    = (N + tb - 1) / tb;
    int grid_E    = (E + tb - 1) / tb;
    int grid_gemm = (N + BM - 1) / BM;
    int nblocks_scan = (N + SCH - 1) / SCH;          // 196
    long long aggth = (long long)N * 32;
    int grid_agg  = (int)((aggth + tb - 1) / tb);

    // CSR build (once, reused by both layers)
    zero_cnt_kernel<<<grid_N, tb>>>(N);
    hist_kernel<<<grid_E, tb>>>(ei, E);
    scan1_kernel<<<nblocks_scan, SCH>>>(N);
    scan2_kernel<<<1, 256>>>(nblocks_scan);
    scan3_kernel<<<grid_N, tb>>>(N);
    fill_kernel<<<grid_E, tb>>>(ei, E);

    // Layer 1
    gemm_dual_kernel<<<grid_gemm, 256>>>(x, W_l1, W_r1, 0, N);
    agg_finish_kernel<<<grid_agg, tb>>>(b1, out, 0, N);

    // Layer 2
    gemm_dual_kernel<<<grid_gemm, 256>>>(x, W_l2, W_r2, 1, N);
    agg_finish_kernel<<<grid_agg, tb>>>(b2, out, 1, N);
}